// round 8
// baseline (speedup 1.0000x reference)
#include <cuda_runtime.h>
#include <cuda_bf16.h>
#include <stdint.h>

#define FD   128        // feature dim
#define MAXN 100000     // nodes
#define MAXE 1664000    // edges (1.6M + slack)
#define CHUNK 1024      // elements per scan block
#define GEMM_M 256      // rows per GEMM block (32 per warp)
#define SROW 136        // smem tile row stride in bf16 elems (272B, conflict-free)
#define SROWB (SROW * 2)

// ---------------------------------------------------------------------------
// Scratch (device globals — no allocation allowed in kernel_launch)
// ---------------------------------------------------------------------------
__device__ float g_dinv[MAXN];
__device__ int   g_cnt  [MAXN];
__device__ int   g_rowptr[MAXN + 1];
__device__ int   g_fill [MAXN];
__device__ int   g_csrc [MAXE];
__device__ int   g_bsum [256];
__device__ int   g_boff [256];
__device__ __align__(128) float g_bufT[(size_t)(MAXN + 256) * FD];
__device__ __align__(128) __nv_bfloat16 g_hh[(size_t)(MAXN + 256) * FD];
__device__ __align__(128) __nv_bfloat16 g_hl[(size_t)(MAXN + 256) * FD];
__device__ __align__(128) __nv_bfloat16 g_W1h[FD * FD];
__device__ __align__(128) __nv_bfloat16 g_W1l[FD * FD];
__device__ __align__(128) __nv_bfloat16 g_W2h[FD * FD];
__device__ __align__(128) __nv_bfloat16 g_W2l[FD * FD];

// ---------------------------------------------------------------------------
// Degree / normalization
// ---------------------------------------------------------------------------
__global__ void k_cnt_init(int n) {
    int i = blockIdx.x * blockDim.x + threadIdx.x;
    if (i < n) g_cnt[i] = 0;
}

__global__ void k_deg_count(const int* __restrict__ dst, int e) {
    int i = blockIdx.x * blockDim.x + threadIdx.x;
    if (i < e) atomicAdd(&g_cnt[dst[i]], 1);
}

__global__ void k_dinv(int n) {
    int i = blockIdx.x * blockDim.x + threadIdx.x;
    if (i < n) g_dinv[i] = rsqrtf(2.0f + (float)g_cnt[i]);
}

// ---------------------------------------------------------------------------
// 3-pass parallel exclusive scan of g_cnt -> g_rowptr / g_fill
// ---------------------------------------------------------------------------
__global__ void __launch_bounds__(256) k_scan1(int n) {
    const int t = threadIdx.x;
    const int base = blockIdx.x * CHUNK + t * 4;
    int s = 0;
#pragma unroll
    for (int m = 0; m < 4; m++) {
        int i = base + m;
        if (i < n) s += g_cnt[i];
    }
#pragma unroll
    for (int o = 16; o > 0; o >>= 1) s += __shfl_down_sync(0xffffffffu, s, o);
    __shared__ int ws[8];
    if ((t & 31) == 0) ws[t >> 5] = s;
    __syncthreads();
    if (t < 8) {
        int v = ws[t];
#pragma unroll
        for (int o = 4; o > 0; o >>= 1) v += __shfl_down_sync(0xffu, v, o);
        if (t == 0) g_bsum[blockIdx.x] = v;
    }
}

__global__ void __launch_bounds__(256) k_scan2(int nb, int n) {
    __shared__ int sh[256];
    int t = threadIdx.x;
    int v = (t < nb) ? g_bsum[t] : 0;
    sh[t] = v;
    __syncthreads();
#pragma unroll
    for (int o = 1; o < 256; o <<= 1) {
        int u = (t >= o) ? sh[t - o] : 0;
        __syncthreads();
        sh[t] += u;
        __syncthreads();
    }
    g_boff[t] = sh[t] - v;
    if (t == nb - 1) g_rowptr[n] = sh[t];
}

__global__ void __launch_bounds__(256) k_scan3(int n) {
    const int t = threadIdx.x;
    const int lane = t & 31;
    const int warp = t >> 5;
    const int base = blockIdx.x * CHUNK + t * 4;

    int c[4];
    int s = 0;
#pragma unroll
    for (int m = 0; m < 4; m++) {
        int i = base + m;
        c[m] = (i < n) ? g_cnt[i] : 0;
        s += c[m];
    }
    int incl = s;
#pragma unroll
    for (int o = 1; o < 32; o <<= 1) {
        int u = __shfl_up_sync(0xffffffffu, incl, o);
        if (lane >= o) incl += u;
    }
    __shared__ int wtot[8];
    if (lane == 31) wtot[warp] = incl;
    __syncthreads();
    int woff = 0;
#pragma unroll
    for (int w = 0; w < 7; w++)
        if (w < warp) woff += wtot[w];
    int pre = g_boff[blockIdx.x] + woff + incl - s;
#pragma unroll
    for (int m = 0; m < 4; m++) {
        int i = base + m;
        if (i < n) {
            g_rowptr[i] = pre;
            g_fill[i]   = pre;
            pre += c[m];
        }
    }
}

__global__ void k_scatter(const int* __restrict__ src, const int* __restrict__ dst, int e) {
    int i = blockIdx.x * blockDim.x + threadIdx.x;
    if (i < e) {
        int d = dst[i];
        int pos = atomicAdd(&g_fill[d], 1);
        g_csrc[pos] = src[i];
    }
}

// ---------------------------------------------------------------------------
// Split helpers: fp32 -> bf16 hi/lo
// ---------------------------------------------------------------------------
__device__ __forceinline__ void split4(float4 v, uint2& hi, uint2& lo) {
    __nv_bfloat16 hx = __float2bfloat16_rn(v.x);
    __nv_bfloat16 hy = __float2bfloat16_rn(v.y);
    __nv_bfloat16 hz = __float2bfloat16_rn(v.z);
    __nv_bfloat16 hw = __float2bfloat16_rn(v.w);
    __nv_bfloat16 lx = __float2bfloat16_rn(v.x - __bfloat162float(hx));
    __nv_bfloat16 ly = __float2bfloat16_rn(v.y - __bfloat162float(hy));
    __nv_bfloat16 lz = __float2bfloat16_rn(v.z - __bfloat162float(hz));
    __nv_bfloat16 lw = __float2bfloat16_rn(v.w - __bfloat162float(hw));
    __nv_bfloat162 h0 = __halves2bfloat162(hx, hy), h1 = __halves2bfloat162(hz, hw);
    __nv_bfloat162 l0 = __halves2bfloat162(lx, ly), l1 = __halves2bfloat162(lz, lw);
    hi = make_uint2(*(uint32_t*)&h0, *(uint32_t*)&h1);
    lo = make_uint2(*(uint32_t*)&l0, *(uint32_t*)&l1);
}

__global__ void __launch_bounds__(256) k_split_x(const float* __restrict__ x, int total4) {
    int i = blockIdx.x * blockDim.x + threadIdx.x;   // float4 index
    if (i >= total4) return;
    float4 v = *(const float4*)(x + (size_t)i * 4);
    uint2 hi, lo;
    split4(v, hi, lo);
    *(uint2*)(g_hh + (size_t)i * 4) = hi;
    *(uint2*)(g_hl + (size_t)i * 4) = lo;
}

// W[k][n] fp32 -> Wh/Wl[n][k] bf16 (transposed: n rows, k contiguous)
__global__ void __launch_bounds__(256) k_wsplit(const float* __restrict__ W,
                                                __nv_bfloat16* __restrict__ Wh,
                                                __nv_bfloat16* __restrict__ Wl) {
    int i = blockIdx.x * blockDim.x + threadIdx.x;   // i = n*128 + k
    if (i >= FD * FD) return;
    int nn = i >> 7, kk = i & 127;
    float w = W[kk * FD + nn];
    __nv_bfloat16 h = __float2bfloat16_rn(w);
    __nv_bfloat16 l = __float2bfloat16_rn(w - __bfloat162float(h));
    Wh[i] = h;
    Wl[i] = l;
}

// ---------------------------------------------------------------------------
// HMMA GEMM: T[n,128] = dinv[row] * (A @ W), fp32 via bf16 3-term split
//   D = Ah@Wh + Ah@Wl + Al@Wh   (fp32 accumulation in registers)
// 256 threads, 256x128 block tile, 32 rows per warp (2 row-halves).
// Each B ldmatrix.x4 feeds 4 MMAs -> B smem bytes per output row halved.
// ---------------------------------------------------------------------------
__device__ __forceinline__ uint32_t smem_to_u32(const void* p) {
    uint32_t a;
    asm("{ .reg .u64 t; cvta.to.shared.u64 t, %1; cvt.u32.u64 %0, t; }"
        : "=r"(a) : "l"(p));
    return a;
}

__device__ __forceinline__ void ldsm_x4(uint32_t& r0, uint32_t& r1,
                                        uint32_t& r2, uint32_t& r3, uint32_t addr) {
    asm volatile("ldmatrix.sync.aligned.m8n8.x4.shared.b16 {%0,%1,%2,%3}, [%4];"
                 : "=r"(r0), "=r"(r1), "=r"(r2), "=r"(r3) : "r"(addr));
}

__device__ __forceinline__ void mma16816(float* c, uint32_t a0, uint32_t a1,
                                         uint32_t a2, uint32_t a3,
                                         uint32_t b0, uint32_t b1) {
    asm volatile(
        "mma.sync.aligned.m16n8k16.row.col.f32.bf16.bf16.f32 "
        "{%0,%1,%2,%3}, {%4,%5,%6,%7}, {%8,%9}, {%0,%1,%2,%3};"
        : "+f"(c[0]), "+f"(c[1]), "+f"(c[2]), "+f"(c[3])
        : "r"(a0), "r"(a1), "r"(a2), "r"(a3), "r"(b0), "r"(b1));
}

// Copy a ROWSx128 bf16 tile (row-major, contiguous) to smem with SROW stride.
template <int ROWS>
__device__ __forceinline__ void load_tile(char* dst, const __nv_bfloat16* g,
                                          int valid_rows) {
    const uint4* gp = (const uint4*)g;   // ROWS*16 uint4, 16 per row
    const int tid = threadIdx.x;
#pragma unroll
    for (int i = 0; i < ROWS / 16; i++) {
        int gi = tid + i * 256;
        int r  = gi >> 4;
        int ch = gi & 15;
        uint4 v = (r < valid_rows) ? gp[gi] : make_uint4(0u, 0u, 0u, 0u);
        *(uint4*)(dst + r * SROWB + ch * 16) = v;
    }
}

#define SM_AH 0
#define SM_AL (256 * SROWB)
#define SM_WH (512 * SROWB)
#define SM_WL (640 * SROWB)
#define SM_TOTAL (768 * SROWB)

__global__ void __launch_bounds__(256, 1)
k_gemm_mma(const __nv_bfloat16* __restrict__ Ah,
           const __nv_bfloat16* __restrict__ Al,
           const __nv_bfloat16* __restrict__ Wh,
           const __nv_bfloat16* __restrict__ Wl,
           float* __restrict__ T, int n) {
    extern __shared__ char smem[];
    const int tid  = threadIdx.x;
    const int lane = tid & 31;
    const int wr0  = (tid >> 5) << 5;    // warp row offset: 0..224 (32 rows/warp)
    const int row0 = blockIdx.x * GEMM_M;
    const int valid = min(GEMM_M, n - row0);

    load_tile<256>(smem + SM_AH, Ah + (size_t)row0 * FD, valid);
    load_tile<256>(smem + SM_AL, Al + (size_t)row0 * FD, valid);
    load_tile<128>(smem + SM_WH, Wh, 128);
    load_tile<128>(smem + SM_WL, Wl, 128);
    __syncthreads();

    const uint32_t sb = smem_to_u32(smem);
    // A frag address for row-half h: row = wr0 + h*16 + (lane&15), +16B lanes 16-31
    const uint32_t aoff = sb + (uint32_t)(wr0 + (lane & 15)) * SROWB
                        + (uint32_t)((lane >> 4) << 4);
    // B x4 address: {n0-7,k0-7},{n0-7,k8-15},{n8-15,k0-7},{n8-15,k8-15}
    const uint32_t boff = sb + (uint32_t)(((lane >> 4) << 3) + (lane & 7)) * SROWB
                        + (uint32_t)(((lane >> 3) & 1) << 4);

    float acc[2][16][4];   // [row-half][n-tile][frag]
#pragma unroll
    for (int h = 0; h < 2; h++)
#pragma unroll
        for (int t = 0; t < 16; t++)
#pragma unroll
            for (int j = 0; j < 4; j++) acc[h][t][j] = 0.0f;

#pragma unroll
    for (int term = 0; term < 3; term++) {
        const uint32_t aBase = aoff + ((term == 2) ? SM_AL : SM_AH);
        const uint32_t bBase = boff + ((term == 1) ? SM_WL : SM_WH);
#pragma unroll
        for (int ks = 0; ks < 8; ks++) {
            uint32_t a0[4], a1[4];
            ldsm_x4(a0[0], a0[1], a0[2], a0[3], aBase + ks * 32);
            ldsm_x4(a1[0], a1[1], a1[2], a1[3], aBase + 16 * SROWB + ks * 32);
#pragma unroll
            for (int nt = 0; nt < 8; nt++) {
                uint32_t b0, b1, b2, b3;
                ldsm_x4(b0, b1, b2, b3, bBase + (uint32_t)nt * 16 * SROWB + ks * 32);
                mma16816(acc[0][nt * 2],     a0[0], a0[1], a0[2], a0[3], b0, b1);
                mma16816(acc[0][nt * 2 + 1], a0[0], a0[1], a0[2], a0[3], b2, b3);
                mma16816(acc[1][nt * 2],     a1[0], a1[1], a1[2], a1[3], b0, b1);
                mma16816(acc[1][nt * 2 + 1], a1[0], a1[1], a1[2], a1[3], b2, b3);
            }
        }
    }

    // epilogue: scale by dinv[row], store fp32
    const int cbase = (lane & 3) << 1;
#pragma unroll
    for (int h = 0; h < 2; h++) {
        const int r0g = row0 + wr0 + h * 16 + (lane >> 2);
        const int r1g = r0g + 8;
        const float dv0 = (r0g < n) ? g_dinv[r0g] : 0.0f;
        const float dv1 = (r1g < n) ? g_dinv[r1g] : 0.0f;
#pragma unroll
        for (int t = 0; t < 16; t++) {
            const int col = t * 8 + cbase;
            if (r0g < n)
                *(float2*)(T + (size_t)r0g * FD + col) =
                    make_float2(dv0 * acc[h][t][0], dv0 * acc[h][t][1]);
            if (r1g < n)
                *(float2*)(T + (size_t)r1g * FD + col) =
                    make_float2(dv1 * acc[h][t][2], dv1 * acc[h][t][3]);
        }
    }
}

// ---------------------------------------------------------------------------
// Gather aggregation: one warp per node.
//   o = dinv[d] * ( sum_{s in N(d)} T[s] + 2*T[d] ) + b
// MODE 0: write bf16 hi/lo split (feeds next layer's MMA)
// MODE 1: write fp32 (final output)
// ---------------------------------------------------------------------------
template <int MODE>
__global__ void __launch_bounds__(256) k_agg(const float* __restrict__ T,
                                             const float* __restrict__ b,
                                             float* __restrict__ out, int n) {
    int node = blockIdx.x * (blockDim.x >> 5) + (threadIdx.x >> 5);
    if (node >= n) return;
    const int lane = threadIdx.x & 31;
    const int c = lane << 2;

    const int beg = g_rowptr[node];
    const int end = g_rowptr[node + 1];

    float4 self = *(const float4*)(T + (size_t)node * FD + c);
    float ax = 2.0f * self.x, ay = 2.0f * self.y;
    float az = 2.0f * self.z, aw = 2.0f * self.w;

    int j = beg;
    for (; j + 3 < end; j += 4) {
        int s0 = __ldg(g_csrc + j);
        int s1 = __ldg(g_csrc + j + 1);
        int s2 = __ldg(g_csrc + j + 2);
        int s3 = __ldg(g_csrc + j + 3);
        float4 v0 = *(const float4*)(T + (size_t)s0 * FD + c);
        float4 v1 = *(const float4*)(T + (size_t)s1 * FD + c);
        float4 v2 = *(const float4*)(T + (size_t)s2 * FD + c);
        float4 v3 = *(const float4*)(T + (size_t)s3 * FD + c);
        ax += v0.x + v1.x + v2.x + v3.x;
        ay += v0.y + v1.y + v2.y + v3.y;
        az += v0.z + v1.z + v2.z + v3.z;
        aw += v0.w + v1.w + v2.w + v3.w;
    }
    for (; j < end; j++) {
        int s = __ldg(g_csrc + j);
        float4 v = *(const float4*)(T + (size_t)s * FD + c);
        ax += v.x; ay += v.y; az += v.z; aw += v.w;
    }

    float dv = g_dinv[node];
    float4 bb = *(const float4*)(b + c);
    float4 o = make_float4(fmaf(dv, ax, bb.x), fmaf(dv, ay, bb.y),
                           fmaf(dv, az, bb.z), fmaf(dv, aw, bb.w));

    if (MODE == 1) {
        *(float4*)(out + (size_t)node * FD + c) = o;
    } else {
        uint2 hi, lo;
        split4(o, hi, lo);
        *(uint2*)(g_hh + (size_t)node * FD + c) = hi;
        *(uint2*)(g_hl + (size_t)node * FD + c) = lo;
    }
}

// ---------------------------------------------------------------------------
// Launcher
// ---------------------------------------------------------------------------
extern "C" void kernel_launch(void* const* d_in, const int* in_sizes, int n_in,
                              void* d_out, int out_size) {
    const float* x  = (const float*)d_in[0];
    const int*   ei = (const int*)  d_in[1];
    const float* W1 = (const float*)d_in[2];
    const float* b1 = (const float*)d_in[3];
    const float* W2 = (const float*)d_in[4];
    const float* b2 = (const float*)d_in[5];
    float* out = (float*)d_out;

    const int n = in_sizes[0] / FD;
    const int e = in_sizes[1] / 2;
    const int* src = ei;
    const int* dst = ei + e;

    float* bufT;
    __nv_bfloat16 *hh, *hl, *w1h, *w1l, *w2h, *w2l;
    cudaGetSymbolAddress((void**)&bufT, g_bufT);
    cudaGetSymbolAddress((void**)&hh,  g_hh);
    cudaGetSymbolAddress((void**)&hl,  g_hl);
    cudaGetSymbolAddress((void**)&w1h, g_W1h);
    cudaGetSymbolAddress((void**)&w1l, g_W1l);
    cudaGetSymbolAddress((void**)&w2h, g_W2h);
    cudaGetSymbolAddress((void**)&w2l, g_W2l);

    cudaFuncSetAttribute(k_gemm_mma, cudaFuncAttributeMaxDynamicSharedMemorySize,
                         SM_TOTAL);

    const int nb = (n + CHUNK - 1) / CHUNK;
    const int ngb = (n + GEMM_M - 1) / GEMM_M;

    // degree + normalization + CSR build
    k_cnt_init <<<(n + 255) / 256, 256>>>(n);
    k_deg_count<<<(e + 255) / 256, 256>>>(dst, e);
    k_dinv     <<<(n + 255) / 256, 256>>>(n);
    k_scan1    <<<nb, 256>>>(n);
    k_scan2    <<<1, 256>>>(nb, n);
    k_scan3    <<<nb, 256>>>(n);
    k_scatter  <<<(e + 255) / 256, 256>>>(src, dst, e);

    // weight + input splits
    k_wsplit  <<<(FD * FD + 255) / 256, 256>>>(W1, w1h, w1l);
    k_wsplit  <<<(FD * FD + 255) / 256, 256>>>(W2, w2h, w2l);
    k_split_x <<<(n * (FD / 4) + 255) / 256, 256>>>(x, n * (FD / 4));

    // layer 1
    k_gemm_mma<<<ngb, 256, SM_TOTAL>>>(hh, hl, w1h, w1l, bufT, n);
    k_agg<0>  <<<(n + 7) / 8, 256>>>(bufT, b1, nullptr, n);
    // layers 2-4
    for (int L = 0; L < 3; L++) {
        k_gemm_mma<<<ngb, 256, SM_TOTAL>>>(hh, hl, w2h, w2l, bufT, n);
        k_agg<0>  <<<(n + 7) / 8, 256>>>(bufT, b2, nullptr, n);
    }
    // layer 5 (final, fp32 output)
    k_gemm_mma<<<ngb, 256, SM_TOTAL>>>(hh, hl, w2h, w2l, bufT, n);
    k_agg<1>  <<<(n + 7) / 8, 256>>>(bufT, b2, out, n);
}

// round 9
// speedup vs baseline: 1.1262x; 1.1262x over previous
#include <cuda_runtime.h>
#include <cuda_bf16.h>
#include <stdint.h>

#define FD   128        // feature dim
#define MAXN 100000     // nodes
#define MAXE 1664000    // edges (1.6M + slack)
#define CHUNK 1024      // elements per scan block
#define TILE_M 128
#define SROW 136        // smem tile row stride in bf16 elems (272B, conflict-free)
#define SROWB (SROW * 2)
#define GEMM_GRID 148

// ---------------------------------------------------------------------------
// Scratch (device globals — no allocation allowed in kernel_launch)
// ---------------------------------------------------------------------------
__device__ float g_dinv[MAXN];
__device__ int   g_cnt  [MAXN];
__device__ int   g_rowptr[MAXN + 1];
__device__ int   g_fill [MAXN];
__device__ int   g_csrc [MAXE];
__device__ int   g_bsum [256];
__device__ int   g_boff [256];
__device__ __align__(128) float g_bufT[(size_t)(MAXN + 256) * FD];
__device__ __align__(128) __nv_bfloat16 g_hh[(size_t)(MAXN + 256) * FD];
__device__ __align__(128) __nv_bfloat16 g_hl[(size_t)(MAXN + 256) * FD];
__device__ __align__(128) __nv_bfloat16 g_W1h[FD * FD];
__device__ __align__(128) __nv_bfloat16 g_W1l[FD * FD];
__device__ __align__(128) __nv_bfloat16 g_W2h[FD * FD];
__device__ __align__(128) __nv_bfloat16 g_W2l[FD * FD];

// ---------------------------------------------------------------------------
// Degree / normalization
// ---------------------------------------------------------------------------
__global__ void k_cnt_init(int n) {
    int i = blockIdx.x * blockDim.x + threadIdx.x;
    if (i < n) g_cnt[i] = 0;
}

__global__ void k_deg_count(const int* __restrict__ dst, int e) {
    int i = blockIdx.x * blockDim.x + threadIdx.x;
    if (i < e) atomicAdd(&g_cnt[dst[i]], 1);
}

__global__ void k_dinv(int n) {
    int i = blockIdx.x * blockDim.x + threadIdx.x;
    if (i < n) g_dinv[i] = rsqrtf(2.0f + (float)g_cnt[i]);
}

// ---------------------------------------------------------------------------
// 3-pass parallel exclusive scan of g_cnt -> g_rowptr / g_fill
// ---------------------------------------------------------------------------
__global__ void __launch_bounds__(256) k_scan1(int n) {
    const int t = threadIdx.x;
    const int base = blockIdx.x * CHUNK + t * 4;
    int s = 0;
#pragma unroll
    for (int m = 0; m < 4; m++) {
        int i = base + m;
        if (i < n) s += g_cnt[i];
    }
#pragma unroll
    for (int o = 16; o > 0; o >>= 1) s += __shfl_down_sync(0xffffffffu, s, o);
    __shared__ int ws[8];
    if ((t & 31) == 0) ws[t >> 5] = s;
    __syncthreads();
    if (t < 8) {
        int v = ws[t];
#pragma unroll
        for (int o = 4; o > 0; o >>= 1) v += __shfl_down_sync(0xffu, v, o);
        if (t == 0) g_bsum[blockIdx.x] = v;
    }
}

__global__ void __launch_bounds__(256) k_scan2(int nb, int n) {
    __shared__ int sh[256];
    int t = threadIdx.x;
    int v = (t < nb) ? g_bsum[t] : 0;
    sh[t] = v;
    __syncthreads();
#pragma unroll
    for (int o = 1; o < 256; o <<= 1) {
        int u = (t >= o) ? sh[t - o] : 0;
        __syncthreads();
        sh[t] += u;
        __syncthreads();
    }
    g_boff[t] = sh[t] - v;
    if (t == nb - 1) g_rowptr[n] = sh[t];
}

__global__ void __launch_bounds__(256) k_scan3(int n) {
    const int t = threadIdx.x;
    const int lane = t & 31;
    const int warp = t >> 5;
    const int base = blockIdx.x * CHUNK + t * 4;

    int c[4];
    int s = 0;
#pragma unroll
    for (int m = 0; m < 4; m++) {
        int i = base + m;
        c[m] = (i < n) ? g_cnt[i] : 0;
        s += c[m];
    }
    int incl = s;
#pragma unroll
    for (int o = 1; o < 32; o <<= 1) {
        int u = __shfl_up_sync(0xffffffffu, incl, o);
        if (lane >= o) incl += u;
    }
    __shared__ int wtot[8];
    if (lane == 31) wtot[warp] = incl;
    __syncthreads();
    int woff = 0;
#pragma unroll
    for (int w = 0; w < 7; w++)
        if (w < warp) woff += wtot[w];
    int pre = g_boff[blockIdx.x] + woff + incl - s;
#pragma unroll
    for (int m = 0; m < 4; m++) {
        int i = base + m;
        if (i < n) {
            g_rowptr[i] = pre;
            g_fill[i]   = pre;
            pre += c[m];
        }
    }
}

__global__ void k_scatter(const int* __restrict__ src, const int* __restrict__ dst, int e) {
    int i = blockIdx.x * blockDim.x + threadIdx.x;
    if (i < e) {
        int d = dst[i];
        int pos = atomicAdd(&g_fill[d], 1);
        g_csrc[pos] = src[i];
    }
}

// ---------------------------------------------------------------------------
// Split helpers: fp32 -> bf16 hi/lo
// ---------------------------------------------------------------------------
__device__ __forceinline__ void split4(float4 v, uint2& hi, uint2& lo) {
    __nv_bfloat16 hx = __float2bfloat16_rn(v.x);
    __nv_bfloat16 hy = __float2bfloat16_rn(v.y);
    __nv_bfloat16 hz = __float2bfloat16_rn(v.z);
    __nv_bfloat16 hw = __float2bfloat16_rn(v.w);
    __nv_bfloat16 lx = __float2bfloat16_rn(v.x - __bfloat162float(hx));
    __nv_bfloat16 ly = __float2bfloat16_rn(v.y - __bfloat162float(hy));
    __nv_bfloat16 lz = __float2bfloat16_rn(v.z - __bfloat162float(hz));
    __nv_bfloat16 lw = __float2bfloat16_rn(v.w - __bfloat162float(hw));
    __nv_bfloat162 h0 = __halves2bfloat162(hx, hy), h1 = __halves2bfloat162(hz, hw);
    __nv_bfloat162 l0 = __halves2bfloat162(lx, ly), l1 = __halves2bfloat162(lz, lw);
    hi = make_uint2(*(uint32_t*)&h0, *(uint32_t*)&h1);
    lo = make_uint2(*(uint32_t*)&l0, *(uint32_t*)&l1);
}

__global__ void __launch_bounds__(256) k_split_x(const float* __restrict__ x, int total4) {
    int i = blockIdx.x * blockDim.x + threadIdx.x;   // float4 index
    if (i >= total4) return;
    float4 v = *(const float4*)(x + (size_t)i * 4);
    uint2 hi, lo;
    split4(v, hi, lo);
    *(uint2*)(g_hh + (size_t)i * 4) = hi;
    *(uint2*)(g_hl + (size_t)i * 4) = lo;
}

// W[k][n] fp32 -> Wh/Wl[n][k] bf16 (transposed: n rows, k contiguous)
__global__ void __launch_bounds__(256) k_wsplit(const float* __restrict__ W,
                                                __nv_bfloat16* __restrict__ Wh,
                                                __nv_bfloat16* __restrict__ Wl) {
    int i = blockIdx.x * blockDim.x + threadIdx.x;   // i = n*128 + k
    if (i >= FD * FD) return;
    int nn = i >> 7, kk = i & 127;
    float w = W[kk * FD + nn];
    __nv_bfloat16 h = __float2bfloat16_rn(w);
    __nv_bfloat16 l = __float2bfloat16_rn(w - __bfloat162float(h));
    Wh[i] = h;
    Wl[i] = l;
}

// ---------------------------------------------------------------------------
// Persistent HMMA GEMM with cp.async double buffering.
//   T[n,128] = dinv[row] * (A @ W),  D = Ah@Wh + Ah@Wl + Al@Wh
// grid=148, 256 thr. W resident in smem; A tiles streamed (2 stages).
// ---------------------------------------------------------------------------
__device__ __forceinline__ uint32_t smem_to_u32(const void* p) {
    uint32_t a;
    asm("{ .reg .u64 t; cvta.to.shared.u64 t, %1; cvt.u32.u64 %0, t; }"
        : "=r"(a) : "l"(p));
    return a;
}

__device__ __forceinline__ void ldsm_x4(uint32_t& r0, uint32_t& r1,
                                        uint32_t& r2, uint32_t& r3, uint32_t addr) {
    asm volatile("ldmatrix.sync.aligned.m8n8.x4.shared.b16 {%0,%1,%2,%3}, [%4];"
                 : "=r"(r0), "=r"(r1), "=r"(r2), "=r"(r3) : "r"(addr));
}

__device__ __forceinline__ void mma16816(float* c, uint32_t a0, uint32_t a1,
                                         uint32_t a2, uint32_t a3,
                                         uint32_t b0, uint32_t b1) {
    asm volatile(
        "mma.sync.aligned.m16n8k16.row.col.f32.bf16.bf16.f32 "
        "{%0,%1,%2,%3}, {%4,%5,%6,%7}, {%8,%9}, {%0,%1,%2,%3};"
        : "+f"(c[0]), "+f"(c[1]), "+f"(c[2]), "+f"(c[3])
        : "r"(a0), "r"(a1), "r"(a2), "r"(a3), "r"(b0), "r"(b1));
}

// cp.async one 128x128 bf16 tile (16B chunks) into smem at SROW stride
__device__ __forceinline__ void cp_tile(uint32_t dstbase, const __nv_bfloat16* g) {
    const char* gp = (const char*)g;
    const int tid = threadIdx.x;
#pragma unroll
    for (int i = 0; i < 8; i++) {
        int gi = tid + i * 256;            // 16B chunk index, 0..2047
        int r  = gi >> 4;
        int ch = gi & 15;
        uint32_t dst = dstbase + (uint32_t)r * SROWB + (uint32_t)ch * 16;
        asm volatile("cp.async.cg.shared.global [%0], [%1], 16;"
                     :: "r"(dst), "l"(gp + (size_t)gi * 16));
    }
}

#define CP_COMMIT() asm volatile("cp.async.commit_group;" ::: "memory")
template <int N>
__device__ __forceinline__ void cp_wait() {
    asm volatile("cp.async.wait_group %0;" :: "n"(N) : "memory");
}

#define TILEB  (128 * SROWB)            // 34816 B per 128x128 tile
#define SM_WH  0
#define SM_WL  TILEB
#define SM_A0H (2 * TILEB)
#define SM_A0L (3 * TILEB)
#define SM_A1H (4 * TILEB)
#define SM_A1L (5 * TILEB)
#define SM_TOTAL (6 * TILEB)            // 208896 B

__global__ void __launch_bounds__(256, 1)
k_gemm_mma(const __nv_bfloat16* __restrict__ Ah,
           const __nv_bfloat16* __restrict__ Al,
           const __nv_bfloat16* __restrict__ Wh,
           const __nv_bfloat16* __restrict__ Wl,
           float* __restrict__ T, int n) {
    extern __shared__ char smem[];
    const uint32_t sb = smem_to_u32(smem);
    const int tid  = threadIdx.x;
    const int lane = tid & 31;
    const int wr0  = (tid >> 5) << 4;    // warp row offset: 0..112
    const int ntiles = (n + TILE_M - 1) / TILE_M;

    // lane-constant fragment offsets
    const uint32_t aoff = (uint32_t)(wr0 + (lane & 15)) * SROWB
                        + (uint32_t)((lane >> 4) << 4);
    const uint32_t boff = (uint32_t)(((lane >> 4) << 3) + (lane & 7)) * SROWB
                        + (uint32_t)(((lane >> 3) & 1) << 4);

    int t0 = blockIdx.x;
    if (t0 >= ntiles) return;

    // group 0: W + first A tile
    cp_tile(sb + SM_WH, Wh);
    cp_tile(sb + SM_WL, Wl);
    cp_tile(sb + SM_A0H, Ah + (size_t)t0 * TILE_M * FD);
    cp_tile(sb + SM_A0L, Al + (size_t)t0 * TILE_M * FD);
    CP_COMMIT();

    int stage = 0;
    for (int t = t0; t < ntiles; t += GEMM_GRID) {
        const int tn = t + GEMM_GRID;
        if (tn < ntiles) {
            const uint32_t dh = sb + (stage ? SM_A0H : SM_A1H);
            const uint32_t dl = sb + (stage ? SM_A0L : SM_A1L);
            cp_tile(dh, Ah + (size_t)tn * TILE_M * FD);
            cp_tile(dl, Al + (size_t)tn * TILE_M * FD);
            CP_COMMIT();
            cp_wait<1>();
        } else {
            cp_wait<0>();
        }
        __syncthreads();

        const uint32_t sAH = sb + (stage ? SM_A1H : SM_A0H);
        const uint32_t sAL = sb + (stage ? SM_A1L : SM_A0L);

        float acc[16][4];
#pragma unroll
        for (int q = 0; q < 16; q++)
#pragma unroll
            for (int j = 0; j < 4; j++) acc[q][j] = 0.0f;

#pragma unroll
        for (int term = 0; term < 3; term++) {
            const uint32_t aBase = aoff + ((term == 2) ? sAL : sAH);
            const uint32_t bBase = boff + sb + ((term == 1) ? SM_WL : SM_WH);

            uint32_t a[8][4];
#pragma unroll
            for (int ks = 0; ks < 8; ks++)
                ldsm_x4(a[ks][0], a[ks][1], a[ks][2], a[ks][3], aBase + ks * 32);

#pragma unroll
            for (int nt = 0; nt < 8; nt++) {
                const uint32_t bnt = bBase + (uint32_t)nt * 16 * SROWB;
#pragma unroll
                for (int ks = 0; ks < 8; ks++) {
                    uint32_t b0, b1, b2, b3;
                    ldsm_x4(b0, b1, b2, b3, bnt + ks * 32);
                    mma16816(acc[nt * 2],     a[ks][0], a[ks][1], a[ks][2], a[ks][3], b0, b1);
                    mma16816(acc[nt * 2 + 1], a[ks][0], a[ks][1], a[ks][2], a[ks][3], b2, b3);
                }
            }
        }

        // epilogue: scale by dinv[row], store fp32
        const int row0 = t * TILE_M;
        const int r0g = row0 + wr0 + (lane >> 2);
        const int r1g = r0g + 8;
        const float dv0 = (r0g < n) ? g_dinv[r0g] : 0.0f;
        const float dv1 = (r1g < n) ? g_dinv[r1g] : 0.0f;
        const int cbase = (lane & 3) << 1;
#pragma unroll
        for (int q = 0; q < 16; q++) {
            const int col = q * 8 + cbase;
            if (r0g < n)
                *(float2*)(T + (size_t)r0g * FD + col) =
                    make_float2(dv0 * acc[q][0], dv0 * acc[q][1]);
            if (r1g < n)
                *(float2*)(T + (size_t)r1g * FD + col) =
                    make_float2(dv1 * acc[q][2], dv1 * acc[q][3]);
        }

        __syncthreads();   // all reads of this stage done before it is refilled
        stage ^= 1;
    }
}

// ---------------------------------------------------------------------------
// Gather aggregation: one warp per node.
//   o = dinv[d] * ( sum_{s in N(d)} T[s] + 2*T[d] ) + b
// MODE 0: write bf16 hi/lo split (feeds next layer's MMA)
// MODE 1: write fp32 (final output)
// ---------------------------------------------------------------------------
template <int MODE>
__global__ void __launch_bounds__(256) k_agg(const float* __restrict__ T,
                                             const float* __restrict__ b,
                                             float* __restrict__ out, int n) {
    int node = blockIdx.x * (blockDim.x >> 5) + (threadIdx.x >> 5);
    if (node >= n) return;
    const int lane = threadIdx.x & 31;
    const int c = lane << 2;

    const int beg = g_rowptr[node];
    const int end = g_rowptr[node + 1];

    float4 self = *(const float4*)(T + (size_t)node * FD + c);
    float ax = 2.0f * self.x, ay = 2.0f * self.y;
    float az = 2.0f * self.z, aw = 2.0f * self.w;

    int j = beg;
    for (; j + 3 < end; j += 4) {
        int s0 = __ldg(g_csrc + j);
        int s1 = __ldg(g_csrc + j + 1);
        int s2 = __ldg(g_csrc + j + 2);
        int s3 = __ldg(g_csrc + j + 3);
        float4 v0 = *(const float4*)(T + (size_t)s0 * FD + c);
        float4 v1 = *(const float4*)(T + (size_t)s1 * FD + c);
        float4 v2 = *(const float4*)(T + (size_t)s2 * FD + c);
        float4 v3 = *(const float4*)(T + (size_t)s3 * FD + c);
        ax += v0.x + v1.x + v2.x + v3.x;
        ay += v0.y + v1.y + v2.y + v3.y;
        az += v0.z + v1.z + v2.z + v3.z;
        aw += v0.w + v1.w + v2.w + v3.w;
    }
    for (; j < end; j++) {
        int s = __ldg(g_csrc + j);
        float4 v = *(const float4*)(T + (size_t)s * FD + c);
        ax += v.x; ay += v.y; az += v.z; aw += v.w;
    }

    float dv = g_dinv[node];
    float4 bb = *(const float4*)(b + c);
    float4 o = make_float4(fmaf(dv, ax, bb.x), fmaf(dv, ay, bb.y),
                           fmaf(dv, az, bb.z), fmaf(dv, aw, bb.w));

    if (MODE == 1) {
        *(float4*)(out + (size_t)node * FD + c) = o;
    } else {
        uint2 hi, lo;
        split4(o, hi, lo);
        *(uint2*)(g_hh + (size_t)node * FD + c) = hi;
        *(uint2*)(g_hl + (size_t)node * FD + c) = lo;
    }
}

// ---------------------------------------------------------------------------
// Launcher
// ---------------------------------------------------------------------------
extern "C" void kernel_launch(void* const* d_in, const int* in_sizes, int n_in,
                              void* d_out, int out_size) {
    const float* x  = (const float*)d_in[0];
    const int*   ei = (const int*)  d_in[1];
    const float* W1 = (const float*)d_in[2];
    const float* b1 = (const float*)d_in[3];
    const float* W2 = (const float*)d_in[4];
    const float* b2 = (const float*)d_in[5];
    float* out = (float*)d_out;

    const int n = in_sizes[0] / FD;
    const int e = in_sizes[1] / 2;
    const int* src = ei;
    const int* dst = ei + e;

    float* bufT;
    __nv_bfloat16 *hh, *hl, *w1h, *w1l, *w2h, *w2l;
    cudaGetSymbolAddress((void**)&bufT, g_bufT);
    cudaGetSymbolAddress((void**)&hh,  g_hh);
    cudaGetSymbolAddress((void**)&hl,  g_hl);
    cudaGetSymbolAddress((void**)&w1h, g_W1h);
    cudaGetSymbolAddress((void**)&w1l, g_W1l);
    cudaGetSymbolAddress((void**)&w2h, g_W2h);
    cudaGetSymbolAddress((void**)&w2l, g_W2l);

    cudaFuncSetAttribute(k_gemm_mma, cudaFuncAttributeMaxDynamicSharedMemorySize,
                         SM_TOTAL);

    const int nb = (n + CHUNK - 1) / CHUNK;

    // degree + normalization + CSR build
    k_cnt_init <<<(n + 255) / 256, 256>>>(n);
    k_deg_count<<<(e + 255) / 256, 256>>>(dst, e);
    k_dinv     <<<(n + 255) / 256, 256>>>(n);
    k_scan1    <<<nb, 256>>>(n);
    k_scan2    <<<1, 256>>>(nb, n);
    k_scan3    <<<nb, 256>>>(n);
    k_scatter  <<<(e + 255) / 256, 256>>>(src, dst, e);

    // weight + input splits
    k_wsplit  <<<(FD * FD + 255) / 256, 256>>>(W1, w1h, w1l);
    k_wsplit  <<<(FD * FD + 255) / 256, 256>>>(W2, w2h, w2l);
    k_split_x <<<(n * (FD / 4) + 255) / 256, 256>>>(x, n * (FD / 4));

    // layer 1
    k_gemm_mma<<<GEMM_GRID, 256, SM_TOTAL>>>(hh, hl, w1h, w1l, bufT, n);
    k_agg<0>  <<<(n + 7) / 8, 256>>>(bufT, b1, nullptr, n);
    // layers 2-4
    for (int L = 0; L < 3; L++) {
        k_gemm_mma<<<GEMM_GRID, 256, SM_TOTAL>>>(hh, hl, w2h, w2l, bufT, n);
        k_agg<0>  <<<(n + 7) / 8, 256>>>(bufT, b2, nullptr, n);
    }
    // layer 5 (final, fp32 output)
    k_gemm_mma<<<GEMM_GRID, 256, SM_TOTAL>>>(hh, hl, w2h, w2l, bufT, n);
    k_agg<1>  <<<(n + 7) / 8, 256>>>(bufT, b2, out, n);
}